// round 5
// baseline (speedup 1.0000x reference)
#include <cuda_runtime.h>
#include <cstdint>

#define D_IN 64
#define D_E 64
#define D_MSG_IN 128
#define D_OUT 128
#define D_APPLY_IN 192
#define MAX_NODES 50000

__device__ float g_hneigh[MAX_NODES * D_OUT];

// ============================ helpers ============================
__device__ __forceinline__ void ffma2(unsigned long long& acc,
                                      unsigned long long a, unsigned long long b) {
    asm("fma.rn.f32x2 %0, %1, %2, %0;" : "+l"(acc) : "l"(a), "l"(b));
}
__device__ __forceinline__ float2 unpack2(unsigned long long v) {
    float2 f;
    asm("mov.b64 {%0, %1}, %2;" : "=f"(f.x), "=f"(f.y) : "l"(v));
    return f;
}
__device__ __forceinline__ void red_add_v4(float* p, float a, float b, float c, float d) {
    asm volatile("red.global.add.v4.f32 [%0], {%1, %2, %3, %4};"
                 :: "l"(p), "f"(a), "f"(b), "f"(c), "f"(d) : "memory");
}
__device__ __forceinline__ uint32_t smem_u32(const void* p) {
    uint32_t a;
    asm("{ .reg .u64 t; cvta.to.shared.u64 t, %1; cvt.u32.u64 %0, t; }" : "=r"(a) : "l"(p));
    return a;
}
__device__ __forceinline__ void ldsm4(uint32_t* r, uint32_t addr) {
    asm volatile("ldmatrix.sync.aligned.m8n8.x4.shared.b16 {%0,%1,%2,%3}, [%4];"
                 : "=r"(r[0]), "=r"(r[1]), "=r"(r[2]), "=r"(r[3]) : "r"(addr));
}
__device__ __forceinline__ void mma_bf16(float* c, const uint32_t* a, uint32_t b0, uint32_t b1) {
    asm volatile("mma.sync.aligned.m16n8k16.row.col.f32.bf16.bf16.f32 "
                 "{%0,%1,%2,%3}, {%4,%5,%6,%7}, {%8,%9}, {%0,%1,%2,%3};"
                 : "+f"(c[0]), "+f"(c[1]), "+f"(c[2]), "+f"(c[3])
                 : "r"(a[0]), "r"(a[1]), "r"(a[2]), "r"(a[3]), "r"(b0), "r"(b1));
}

__global__ void zero_hneigh_kernel(int n4) {
    int i = blockIdx.x * blockDim.x + threadIdx.x;
    if (i < n4)
        reinterpret_cast<float4*>(g_hneigh)[i] = make_float4(0.f, 0.f, 0.f, 0.f);
}

// =====================================================================
// Edge message kernel v4: mma.sync bf16 split-2 GEMM (3 passes).
// Tile = 128 edges x 128 cols per CTA. Warp grid 4(m) x 2(n): each warp
// m32 x n64. Swizzled bf16 tiles in smem for conflict-free ldmatrix.
// =====================================================================
// smem bytes: Whi 32K | Wlo 32K | Xhi 32K | Xlo 32K | bias 512
#define SM_WHI  0u
#define SM_WLO  32768u
#define SM_XHI  65536u
#define SM_XLO  98304u
#define SM_BIAS 131072u
#define SM_EDGE_BYTES 131584u

// byte offset inside a 128x128-bf16 tile: row-major 256B rows, 16B-chunk XOR swizzle
__device__ __forceinline__ uint32_t toff(int row, int kchunk) {
    return ((uint32_t)row << 8) + ((uint32_t)(kchunk ^ (row & 7)) << 4);
}

__global__ __launch_bounds__(256, 1)
void edge_msg_kernel(const float* __restrict__ nfeats,
                     const float* __restrict__ efeats,
                     const float* __restrict__ Wmsg,
                     const float* __restrict__ bmsg,
                     const int* __restrict__ src,
                     const int* __restrict__ dst,
                     int E)
{
    extern __shared__ char smem[];
    const uint32_t sb = smem_u32(smem);
    const int tid  = threadIdx.x;
    const int lane = tid & 31;
    const int wid  = tid >> 5;

    // ---- W split: Wt[n][k] = Wmsg[k][n], hi/lo bf16, swizzled ----
    for (int i = tid; i < 128 * 128; i += 256) {
        int n = i >> 7, k = i & 127;
        float w = Wmsg[k * 128 + n];
        uint32_t hb;
        asm("cvt.rn.bf16x2.f32 %0, %1, %2;" : "=r"(hb) : "f"(0.f), "f"(w));
        float hf = __uint_as_float(hb << 16);
        uint32_t lb;
        asm("cvt.rn.bf16x2.f32 %0, %1, %2;" : "=r"(lb) : "f"(0.f), "f"(w - hf));
        uint32_t off = toff(n, k >> 3) + (k & 7) * 2;
        *reinterpret_cast<uint16_t*>(smem + SM_WHI + off) = (uint16_t)hb;
        *reinterpret_cast<uint16_t*>(smem + SM_WLO + off) = (uint16_t)lb;
    }
    if (tid < 128) reinterpret_cast<float*>(smem + SM_BIAS)[tid] = bmsg[tid];
    __syncthreads();

    // ---- warp tiling ----
    const int mbase = (wid & 3) * 32;
    const int nbase = (wid >> 2) * 64;
    const int mrel  = lane & 15;
    const int khA   = lane >> 4;
    const int nrel  = (lane & 7) + ((lane >> 4) << 3);
    const int khB   = (lane >> 3) & 1;
    const uint32_t swzA = (uint32_t)(mrel & 7);
    const uint32_t swzB = (uint32_t)(nrel & 7);
    uint32_t aRow[2], bRow[4];
    #pragma unroll
    for (int mt = 0; mt < 2; ++mt) aRow[mt] = (uint32_t)(mbase + mt * 16 + mrel) << 8;
    #pragma unroll
    for (int g = 0; g < 4; ++g) bRow[g] = (uint32_t)(nbase + g * 16 + nrel) << 8;

    // bias pairs for this lane's cols: c = nbase + nt*8 + (lane&3)*2
    float bx[8], by[8];
    {
        const float* bsm = reinterpret_cast<const float*>(smem + SM_BIAS);
        #pragma unroll
        for (int nt = 0; nt < 8; ++nt) {
            float2 bb = *reinterpret_cast<const float2*>(bsm + nbase + nt * 8 + (lane & 3) * 2);
            bx[nt] = bb.x; by[nt] = bb.y;
        }
    }

    float acc[2][8][4];
    #pragma unroll
    for (int mt = 0; mt < 2; ++mt)
        #pragma unroll
        for (int nt = 0; nt < 8; ++nt)
            #pragma unroll
            for (int q = 0; q < 4; ++q) acc[mt][nt][q] = 0.f;

    const uint32_t aBase[3] = {sb + SM_XHI, sb + SM_XHI, sb + SM_XLO};
    const uint32_t bBase[3] = {sb + SM_WHI, sb + SM_WLO, sb + SM_WHI};

    const int tiles = (E + 127) >> 7;
    for (int tile = blockIdx.x; tile < tiles; tile += gridDim.x) {
        const int base = tile << 7;

        // ---- gather + split-convert: warp wid handles rows wid*16..+15 ----
        {
            const int r0 = wid << 4;
            int ee = base + r0 + (lane & 15);
            int sv = (lane < 16 && ee < E) ? src[ee] : 0;
            const int k = lane * 4;
            #pragma unroll 4
            for (int r = 0; r < 16; ++r) {
                const int row = r0 + r;
                const int eg  = base + row;
                const int s   = __shfl_sync(0xffffffffu, sv, r);
                float4 v;
                if (eg < E) {
                    if (k < D_IN)
                        v = *reinterpret_cast<const float4*>(nfeats + (size_t)s * D_IN + k);
                    else
                        v = *reinterpret_cast<const float4*>(efeats + (size_t)eg * D_E + (k - D_IN));
                } else {
                    v = make_float4(0.f, 0.f, 0.f, 0.f);
                }
                uint32_t h01, h23;
                asm("cvt.rn.bf16x2.f32 %0, %1, %2;" : "=r"(h01) : "f"(v.y), "f"(v.x));
                asm("cvt.rn.bf16x2.f32 %0, %1, %2;" : "=r"(h23) : "f"(v.w), "f"(v.z));
                float hx = __uint_as_float(h01 << 16);
                float hy = __uint_as_float(h01 & 0xffff0000u);
                float hz = __uint_as_float(h23 << 16);
                float hw = __uint_as_float(h23 & 0xffff0000u);
                uint32_t l01, l23;
                asm("cvt.rn.bf16x2.f32 %0, %1, %2;" : "=r"(l01) : "f"(v.y - hy), "f"(v.x - hx));
                asm("cvt.rn.bf16x2.f32 %0, %1, %2;" : "=r"(l23) : "f"(v.w - hw), "f"(v.z - hz));
                const uint32_t off = toff(row, lane >> 1) + (lane & 1) * 8;
                *reinterpret_cast<uint2*>(smem + SM_XHI + off) = make_uint2(h01, h23);
                *reinterpret_cast<uint2*>(smem + SM_XLO + off) = make_uint2(l01, l23);
            }
        }
        __syncthreads();

        // ---- 3 MMA passes: (Xhi,Whi), (Xhi,Wlo), (Xlo,Whi) ----
        #pragma unroll 1
        for (int pass = 0; pass < 3; ++pass) {
            const uint32_t ab = aBase[pass];
            const uint32_t bb = bBase[pass];
            #pragma unroll
            for (int kc = 0; kc < 8; ++kc) {
                const uint32_t ka = (uint32_t)(((kc << 1) | khA) ^ swzA) << 4;
                const uint32_t kb = (uint32_t)(((kc << 1) | khB) ^ swzB) << 4;
                uint32_t afr[2][4], bfr[4][4];
                #pragma unroll
                for (int mt = 0; mt < 2; ++mt) ldsm4(afr[mt], ab + aRow[mt] + ka);
                #pragma unroll
                for (int g = 0; g < 4; ++g) ldsm4(bfr[g], bb + bRow[g] + kb);
                #pragma unroll
                for (int mt = 0; mt < 2; ++mt)
                    #pragma unroll
                    for (int nt = 0; nt < 8; ++nt)
                        mma_bf16(acc[mt][nt], afr[mt],
                                 bfr[nt >> 1][(nt & 1) * 2],
                                 bfr[nt >> 1][(nt & 1) * 2 + 1]);
            }
        }

        // ---- epilogue: bias+relu, pair-merge via shfl, red.v4 scatter ----
        #pragma unroll
        for (int mt = 0; mt < 2; ++mt) {
            const int rtop = mbase + mt * 16 + (lane >> 2);
            const int etop = base + rtop;
            const int ebot = etop + 8;
            const int dtop = (etop < E) ? dst[etop] : 0;
            const int dbot = (ebot < E) ? dst[ebot] : 0;
            const int cb   = nbase + (lane & 2) * 2;
            #pragma unroll
            for (int nt = 0; nt < 8; ++nt) {
                float v0 = fmaxf(acc[mt][nt][0] + bx[nt], 0.f);
                float v1 = fmaxf(acc[mt][nt][1] + by[nt], 0.f);
                float v2 = fmaxf(acc[mt][nt][2] + bx[nt], 0.f);
                float v3 = fmaxf(acc[mt][nt][3] + by[nt], 0.f);
                float w0 = __shfl_xor_sync(0xffffffffu, v0, 1);
                float w1 = __shfl_xor_sync(0xffffffffu, v1, 1);
                float w2 = __shfl_xor_sync(0xffffffffu, v2, 1);
                float w3 = __shfl_xor_sync(0xffffffffu, v3, 1);
                if (!(lane & 1)) {
                    if (etop < E)
                        red_add_v4(g_hneigh + (size_t)dtop * D_OUT + cb + nt * 8, v0, v1, w0, w1);
                    if (ebot < E)
                        red_add_v4(g_hneigh + (size_t)dbot * D_OUT + cb + nt * 8, v2, v3, w2, w3);
                }
                acc[mt][nt][0] = 0.f; acc[mt][nt][1] = 0.f;
                acc[mt][nt][2] = 0.f; acc[mt][nt][3] = 0.f;
            }
        }
        __syncthreads();
    }
}

// =====================================================================
// Apply kernel (unchanged from R3): 8 nodes/warp, f32x2 packed along k.
// =====================================================================
#define A_WT 0
#define A_BIAS 24576
#define A_X 24704
#define A_SMEM_FLOATS 37248

__global__ __launch_bounds__(256, 1)
void apply_kernel(const float* __restrict__ nfeats,
                  const float* __restrict__ Wap,
                  const float* __restrict__ bap,
                  float* __restrict__ out,
                  int N)
{
    extern __shared__ float sm[];
    float* wsm  = sm + A_WT;
    float* bsm  = sm + A_BIAS;
    float* xall = sm + A_X;

    for (int half = 0; half < 2; ++half) {
        for (int i = threadIdx.x; i < 3072; i += 256)
            reinterpret_cast<float4*>(xall)[i] =
                reinterpret_cast<const float4*>(Wap + half * 12288)[i];
        __syncthreads();
        for (int i = threadIdx.x; i < 12288; i += 256) {
            int kl = i >> 7, c = i & 127, k = half * 96 + kl;
            wsm[c * 192 + (((k >> 2) ^ ((c >> 2) & 7)) << 2) + (k & 3)] = xall[i];
        }
        __syncthreads();
    }
    if (threadIdx.x < 128) bsm[threadIdx.x] = bap[threadIdx.x];
    __syncthreads();

    const int lane = threadIdx.x & 31;
    const int warp = threadIdx.x >> 5;
    const int gw   = blockIdx.x * 8 + warp;
    const int nw   = gridDim.x * 8;
    const int s7   = lane & 7;

    float* xw = xall + warp * (8 * 196);
    const float* wl = wsm + (lane * 4) * 192;
    const float4 bias4 = *reinterpret_cast<const float4*>(bsm + lane * 4);

    const int h  = lane >> 4;
    const int j  = lane & 15;
    const int cg = j * 12;

    unsigned long long acc[8][4];
    #pragma unroll
    for (int e = 0; e < 8; ++e)
        #pragma unroll
        for (int c = 0; c < 4; ++c) acc[e][c] = 0ull;

    const int tiles = (N + 7) >> 3;
    for (int tile = gw; tile < tiles; tile += nw) {
        const int base = tile * 8;

        #pragma unroll
        for (int r = 0; r < 4; ++r) {
            int nl = r * 2 + h;
            int ng = base + nl;
            if (ng < N) {
                #pragma unroll
                for (int q = 0; q < 3; ++q) {
                    int off = cg + q * 4;
                    float4 v;
                    if (off < D_IN)
                        v = *reinterpret_cast<const float4*>(nfeats + (size_t)ng * D_IN + off);
                    else
                        v = *reinterpret_cast<const float4*>(g_hneigh + (size_t)ng * D_OUT + (off - D_IN));
                    *reinterpret_cast<float4*>(xw + nl * 196 + off) = v;
                }
            }
        }
        __syncwarp();

        #pragma unroll 4
        for (int t = 0; t < 48; ++t) {
            const int wq = ((t ^ s7) << 2);
            ulonglong2 w0 = *reinterpret_cast<const ulonglong2*>(wl + wq);
            ulonglong2 w1 = *reinterpret_cast<const ulonglong2*>(wl + 192 + wq);
            ulonglong2 w2 = *reinterpret_cast<const ulonglong2*>(wl + 384 + wq);
            ulonglong2 w3 = *reinterpret_cast<const ulonglong2*>(wl + 576 + wq);
            #pragma unroll
            for (int e = 0; e < 8; ++e) {
                ulonglong2 xv = *reinterpret_cast<const ulonglong2*>(xw + e * 196 + t * 4);
                ffma2(acc[e][0], xv.x, w0.x); ffma2(acc[e][0], xv.y, w0.y);
                ffma2(acc[e][1], xv.x, w1.x); ffma2(acc[e][1], xv.y, w1.y);
                ffma2(acc[e][2], xv.x, w2.x); ffma2(acc[e][2], xv.y, w2.y);
                ffma2(acc[e][3], xv.x, w3.x); ffma2(acc[e][3], xv.y, w3.y);
            }
        }

        #pragma unroll
        for (int e = 0; e < 8; ++e) {
            int ng = base + e;
            float2 f0 = unpack2(acc[e][0]);
            float2 f1 = unpack2(acc[e][1]);
            float2 f2 = unpack2(acc[e][2]);
            float2 f3 = unpack2(acc[e][3]);
            float4 o;
            o.x = fmaxf(f0.x + f0.y + bias4.x, 0.f);
            o.y = fmaxf(f1.x + f1.y + bias4.y, 0.f);
            o.z = fmaxf(f2.x + f2.y + bias4.z, 0.f);
            o.w = fmaxf(f3.x + f3.y + bias4.w, 0.f);
            if (ng < N)
                *reinterpret_cast<float4*>(out + (size_t)ng * D_OUT + lane * 4) = o;
            acc[e][0] = 0ull; acc[e][1] = 0ull; acc[e][2] = 0ull; acc[e][3] = 0ull;
        }
        __syncwarp();
    }
}

extern "C" void kernel_launch(void* const* d_in, const int* in_sizes, int n_in,
                              void* d_out, int out_size)
{
    const float* nfeats = (const float*)d_in[0];
    const float* efeats = (const float*)d_in[1];
    const float* Wmsg   = (const float*)d_in[2];
    const float* bmsg   = (const float*)d_in[3];
    const float* Wap    = (const float*)d_in[4];
    const float* bap    = (const float*)d_in[5];
    const int*   src    = (const int*)d_in[6];
    const int*   dst    = (const int*)d_in[7];

    const int E = in_sizes[6];
    const int N = in_sizes[0] / D_IN;

    const size_t smem_edge  = SM_EDGE_BYTES;                    // 131584 B
    const size_t smem_apply = A_SMEM_FLOATS * sizeof(float);    // 148992 B
    cudaFuncSetAttribute(edge_msg_kernel, cudaFuncAttributeMaxDynamicSharedMemorySize, (int)smem_edge);
    cudaFuncSetAttribute(apply_kernel,    cudaFuncAttributeMaxDynamicSharedMemorySize, (int)smem_apply);

    const int n4 = (N * D_OUT) / 4;
    zero_hneigh_kernel<<<(n4 + 255) / 256, 256>>>(n4);
    edge_msg_kernel<<<148, 256, smem_edge>>>(nfeats, efeats, Wmsg, bmsg, src, dst, E);
    apply_kernel<<<152, 256, smem_apply>>>(nfeats, Wap, bap, (float*)d_out, N);
}

// round 7
// speedup vs baseline: 1.4576x; 1.4576x over previous
#include <cuda_runtime.h>
#include <cstdint>

#define D_IN 64
#define D_E 64
#define D_MSG_IN 128
#define D_OUT 128
#define D_APPLY_IN 192
#define MAX_NODES 50000
#define MAX_EDGES 800000

__device__ float g_hneigh[MAX_NODES * D_OUT];
// packed bf16 split rows: per row 128B hi + 128B lo
__device__ __align__(16) unsigned char g_nconv[(size_t)MAX_NODES * 256];
__device__ __align__(16) unsigned char g_econv[(size_t)MAX_EDGES * 256];

// ============================ helpers ============================
__device__ __forceinline__ void ffma2(unsigned long long& acc,
                                      unsigned long long a, unsigned long long b) {
    asm("fma.rn.f32x2 %0, %1, %2, %0;" : "+l"(acc) : "l"(a), "l"(b));
}
__device__ __forceinline__ float2 unpack2(unsigned long long v) {
    float2 f;
    asm("mov.b64 {%0, %1}, %2;" : "=f"(f.x), "=f"(f.y) : "l"(v));
    return f;
}
__device__ __forceinline__ void red_add_v4(float* p, float a, float b, float c, float d) {
    asm volatile("red.global.add.v4.f32 [%0], {%1, %2, %3, %4};"
                 :: "l"(p), "f"(a), "f"(b), "f"(c), "f"(d) : "memory");
}
__device__ __forceinline__ uint32_t smem_u32(const void* p) {
    uint32_t a;
    asm("{ .reg .u64 t; cvta.to.shared.u64 t, %1; cvt.u32.u64 %0, t; }" : "=r"(a) : "l"(p));
    return a;
}
__device__ __forceinline__ void ldsm4(uint32_t* r, uint32_t addr) {
    asm volatile("ldmatrix.sync.aligned.m8n8.x4.shared.b16 {%0,%1,%2,%3}, [%4];"
                 : "=r"(r[0]), "=r"(r[1]), "=r"(r[2]), "=r"(r[3]) : "r"(addr));
}
__device__ __forceinline__ void mma_bf16(float* c, const uint32_t* a, uint32_t b0, uint32_t b1) {
    asm volatile("mma.sync.aligned.m16n8k16.row.col.f32.bf16.bf16.f32 "
                 "{%0,%1,%2,%3}, {%4,%5,%6,%7}, {%8,%9}, {%0,%1,%2,%3};"
                 : "+f"(c[0]), "+f"(c[1]), "+f"(c[2]), "+f"(c[3])
                 : "r"(a[0]), "r"(a[1]), "r"(a[2]), "r"(a[3]), "r"(b0), "r"(b1));
}
__device__ __forceinline__ void cpa16(uint32_t dst, const void* src) {
    asm volatile("cp.async.cg.shared.global [%0], [%1], 16;" :: "r"(dst), "l"(src));
}
#define CP_COMMIT() asm volatile("cp.async.commit_group;" ::: "memory")
#define CP_WAIT1()  asm volatile("cp.async.wait_group 1;" ::: "memory")
__device__ __forceinline__ void sts_zero16(uint32_t dst) {
    asm volatile("st.shared.v4.b32 [%0], {%1,%1,%1,%1};" :: "r"(dst), "r"(0u));
}

__global__ void zero_hneigh_kernel(int n4) {
    int i = blockIdx.x * blockDim.x + threadIdx.x;
    if (i < n4)
        reinterpret_cast<float4*>(g_hneigh)[i] = make_float4(0.f, 0.f, 0.f, 0.f);
}

// ---------- prepass: fp32 rows -> packed bf16 hi/lo rows (256B/row) ----------
__global__ void conv_split_kernel(const float4* __restrict__ in,
                                  unsigned char* __restrict__ out, int nchunks) {
    int i = blockIdx.x * blockDim.x + threadIdx.x;
    if (i >= nchunks) return;
    int row = i >> 4, q = i & 15;
    float4 v = in[i];
    uint32_t h01, h23;
    asm("cvt.rn.bf16x2.f32 %0, %1, %2;" : "=r"(h01) : "f"(v.y), "f"(v.x));
    asm("cvt.rn.bf16x2.f32 %0, %1, %2;" : "=r"(h23) : "f"(v.w), "f"(v.z));
    float hx = __uint_as_float(h01 << 16);
    float hy = __uint_as_float(h01 & 0xffff0000u);
    float hz = __uint_as_float(h23 << 16);
    float hw = __uint_as_float(h23 & 0xffff0000u);
    uint32_t l01, l23;
    asm("cvt.rn.bf16x2.f32 %0, %1, %2;" : "=r"(l01) : "f"(v.y - hy), "f"(v.x - hx));
    asm("cvt.rn.bf16x2.f32 %0, %1, %2;" : "=r"(l23) : "f"(v.w - hw), "f"(v.z - hz));
    unsigned char* o = out + (size_t)row * 256;
    *reinterpret_cast<uint2*>(o + q * 8)       = make_uint2(h01, h23);
    *reinterpret_cast<uint2*>(o + 128 + q * 8) = make_uint2(l01, l23);
}

// =====================================================================
// Edge kernel v5b: double-buffered cp.async gather + bf16 split-2 mma.sync
// (R6 with the divergent-shfl deadlock fixed: shfl hoisted to all lanes)
// =====================================================================
#define SM_WHI  0u
#define SM_WLO  32768u
#define SM_XHI0 65536u
#define SM_XLO0 98304u
#define SM_XHI1 131072u
#define SM_XLO1 163840u
#define SM_BIAS 196608u
#define SM_EDGE_BYTES 197120u

// byte offset inside a 128x128-bf16 tile: 256B rows, 16B-chunk XOR swizzle
__device__ __forceinline__ uint32_t toff(int row, int kchunk) {
    return ((uint32_t)row << 8) + ((uint32_t)(kchunk ^ (row & 7)) << 4);
}

__global__ __launch_bounds__(256, 1)
void edge_msg_kernel(const float* __restrict__ Wmsg,
                     const float* __restrict__ bmsg,
                     const int* __restrict__ src,
                     const int* __restrict__ dst,
                     int E)
{
    extern __shared__ char smem[];
    const uint32_t sb = smem_u32(smem);
    const int tid  = threadIdx.x;
    const int lane = tid & 31;
    const int wid  = tid >> 5;

    // ---- W split to smem: Wt[n][k] = Wmsg[k][n], hi/lo bf16, swizzled ----
    for (int i = tid; i < 128 * 128; i += 256) {
        int n = i >> 7, k = i & 127;
        float w = Wmsg[k * 128 + n];
        uint32_t hb;
        asm("cvt.rn.bf16x2.f32 %0, %1, %2;" : "=r"(hb) : "f"(0.f), "f"(w));
        float hf = __uint_as_float(hb << 16);
        uint32_t lb;
        asm("cvt.rn.bf16x2.f32 %0, %1, %2;" : "=r"(lb) : "f"(0.f), "f"(w - hf));
        uint32_t off = toff(n, k >> 3) + (k & 7) * 2;
        *reinterpret_cast<uint16_t*>(smem + SM_WHI + off) = (uint16_t)hb;
        *reinterpret_cast<uint16_t*>(smem + SM_WLO + off) = (uint16_t)lb;
    }
    if (tid < 128) reinterpret_cast<float*>(smem + SM_BIAS)[tid] = bmsg[tid];
    __syncthreads();

    // ---- per-thread constants for gather ----
    const int g_rr   = lane & 15;
    const int g_row  = (wid << 4) + g_rr;
    const int g_half = lane >> 4;

    // ---- warp tiling for MMA (4m x 2n, warp tile m32 x n64) ----
    const int mbase = (wid & 3) * 32;
    const int nbase = (wid >> 2) * 64;
    const int mrel  = lane & 15;
    const int khA   = lane >> 4;
    const int nrel  = (lane & 7) + ((lane >> 4) << 3);
    const int khB   = (lane >> 3) & 1;
    const uint32_t swzA = (uint32_t)(mrel & 7);
    const uint32_t swzB = (uint32_t)(nrel & 7);
    uint32_t aRow[2], bRow[4];
    #pragma unroll
    for (int mt = 0; mt < 2; ++mt) aRow[mt] = (uint32_t)(mbase + mt * 16 + mrel) << 8;
    #pragma unroll
    for (int g = 0; g < 4; ++g) bRow[g] = (uint32_t)(nbase + g * 16 + nrel) << 8;

    // bias pairs: c = nbase + nt*8 + (lane&3)*2
    float bx[8], by[8];
    {
        const float* bsm = reinterpret_cast<const float*>(smem + SM_BIAS);
        #pragma unroll
        for (int nt = 0; nt < 8; ++nt) {
            float2 bb = *reinterpret_cast<const float2*>(bsm + nbase + nt * 8 + (lane & 3) * 2);
            bx[nt] = bb.x; by[nt] = bb.y;
        }
    }

    float acc[2][8][4];
    #pragma unroll
    for (int mt = 0; mt < 2; ++mt)
        #pragma unroll
        for (int nt = 0; nt < 8; ++nt)
            #pragma unroll
            for (int q = 0; q < 4; ++q) acc[mt][nt][q] = 0.f;

    const uint32_t xhiS[2] = {sb + SM_XHI0, sb + SM_XHI1};
    const uint32_t xloS[2] = {sb + SM_XLO0, sb + SM_XLO1};
    const uint32_t wHi = sb + SM_WHI, wLo = sb + SM_WLO;

    const int tiles = (E + 127) >> 7;
    const int grid  = gridDim.x;

    // ---- gather issue for one tile into a stage (all lanes convergent) ----
    auto issue_tile = [&](int base, uint32_t xhi, uint32_t xlo) {
        int sv = 0;
        {
            int ee = base + (wid << 4) + g_rr;
            if (lane < 16 && ee < E) sv = src[ee];
        }
        // ALL 32 lanes execute the shuffle (fix for R6 deadlock)
        const int s = __shfl_sync(0xffffffffu, sv, g_rr);
        const int eg = base + g_row;
        const bool valid = (eg < E);
        const unsigned char* srow = (g_half == 0)
            ? (g_nconv + (size_t)s * 256)
            : (g_econv + (size_t)eg * 256);
        #pragma unroll
        for (int c = 0; c < 8; ++c) {
            const int kchunk = g_half ? (8 + c) : c;
            const uint32_t dhi = xhi + toff(g_row, kchunk);
            const uint32_t dlo = xlo + toff(g_row, kchunk);
            if (valid) {
                cpa16(dhi, srow + c * 16);
                cpa16(dlo, srow + 128 + c * 16);
            } else {
                sts_zero16(dhi);
                sts_zero16(dlo);
            }
        }
    };

    // ---- pipelined main loop ----
    int t = blockIdx.x;
    int cur = 0;
    if (t < tiles) issue_tile(t << 7, xhiS[0], xloS[0]);
    CP_COMMIT();

    for (; t < tiles; t += grid) {
        const int tn = t + grid;
        if (tn < tiles) issue_tile(tn << 7, xhiS[cur ^ 1], xloS[cur ^ 1]);
        CP_COMMIT();
        CP_WAIT1();
        __syncthreads();

        const uint32_t xhi = xhiS[cur], xlo = xloS[cur];
        const int base = t << 7;

        // ---- MMA: Xhi*Whi + Xlo*Whi + Xhi*Wlo ----
        #pragma unroll
        for (int kc = 0; kc < 8; ++kc) {
            const uint32_t ka = (uint32_t)(((kc << 1) | khA) ^ swzA) << 4;
            const uint32_t kb = (uint32_t)(((kc << 1) | khB) ^ swzB) << 4;
            uint32_t ahi[2][4], alo[2][4], bfr[4][4];
            #pragma unroll
            for (int mt = 0; mt < 2; ++mt) ldsm4(ahi[mt], xhi + aRow[mt] + ka);
            #pragma unroll
            for (int mt = 0; mt < 2; ++mt) ldsm4(alo[mt], xlo + aRow[mt] + ka);
            #pragma unroll
            for (int g = 0; g < 4; ++g) ldsm4(bfr[g], wHi + bRow[g] + kb);
            #pragma unroll
            for (int mt = 0; mt < 2; ++mt)
                #pragma unroll
                for (int nt = 0; nt < 8; ++nt)
                    mma_bf16(acc[mt][nt], ahi[mt],
                             bfr[nt >> 1][(nt & 1) * 2], bfr[nt >> 1][(nt & 1) * 2 + 1]);
            #pragma unroll
            for (int mt = 0; mt < 2; ++mt)
                #pragma unroll
                for (int nt = 0; nt < 8; ++nt)
                    mma_bf16(acc[mt][nt], alo[mt],
                             bfr[nt >> 1][(nt & 1) * 2], bfr[nt >> 1][(nt & 1) * 2 + 1]);
            #pragma unroll
            for (int g = 0; g < 4; ++g) ldsm4(bfr[g], wLo + bRow[g] + kb);
            #pragma unroll
            for (int mt = 0; mt < 2; ++mt)
                #pragma unroll
                for (int nt = 0; nt < 8; ++nt)
                    mma_bf16(acc[mt][nt], ahi[mt],
                             bfr[nt >> 1][(nt & 1) * 2], bfr[nt >> 1][(nt & 1) * 2 + 1]);
        }

        // ---- epilogue: bias+relu, pair-merge via shfl, red.v4 scatter ----
        #pragma unroll
        for (int mt = 0; mt < 2; ++mt) {
            const int rtop = mbase + mt * 16 + (lane >> 2);
            const int etop = base + rtop;
            const int ebot = etop + 8;
            const int dtop = (etop < E) ? dst[etop] : 0;
            const int dbot = (ebot < E) ? dst[ebot] : 0;
            const int cb   = nbase + (lane & 2) * 2;
            #pragma unroll
            for (int nt = 0; nt < 8; ++nt) {
                float v0 = fmaxf(acc[mt][nt][0] + bx[nt], 0.f);
                float v1 = fmaxf(acc[mt][nt][1] + by[nt], 0.f);
                float v2 = fmaxf(acc[mt][nt][2] + bx[nt], 0.f);
                float v3 = fmaxf(acc[mt][nt][3] + by[nt], 0.f);
                float w0 = __shfl_xor_sync(0xffffffffu, v0, 1);
                float w1 = __shfl_xor_sync(0xffffffffu, v1, 1);
                float w2 = __shfl_xor_sync(0xffffffffu, v2, 1);
                float w3 = __shfl_xor_sync(0xffffffffu, v3, 1);
                if (!(lane & 1)) {
                    if (etop < E)
                        red_add_v4(g_hneigh + (size_t)dtop * D_OUT + cb + nt * 8, v0, v1, w0, w1);
                    if (ebot < E)
                        red_add_v4(g_hneigh + (size_t)dbot * D_OUT + cb + nt * 8, v2, v3, w2, w3);
                }
                acc[mt][nt][0] = 0.f; acc[mt][nt][1] = 0.f;
                acc[mt][nt][2] = 0.f; acc[mt][nt][3] = 0.f;
            }
        }
        __syncthreads();
        cur ^= 1;
    }
}

// =====================================================================
// Apply kernel (R3): 8 nodes/warp, f32x2 packed along k.
// =====================================================================
#define A_WT 0
#define A_BIAS 24576
#define A_X 24704
#define A_SMEM_FLOATS 37248

__global__ __launch_bounds__(256, 1)
void apply_kernel(const float* __restrict__ nfeats,
                  const float* __restrict__ Wap,
                  const float* __restrict__ bap,
                  float* __restrict__ out,
                  int N)
{
    extern __shared__ float sm[];
    float* wsm  = sm + A_WT;
    float* bsm  = sm + A_BIAS;
    float* xall = sm + A_X;

    for (int half = 0; half < 2; ++half) {
        for (int i = threadIdx.x; i < 3072; i += 256)
            reinterpret_cast<float4*>(xall)[i] =
                reinterpret_cast<const float4*>(Wap + half * 12288)[i];
        __syncthreads();
        for (int i = threadIdx.x; i < 12288; i += 256) {
            int kl = i >> 7, c = i & 127, k = half * 96 + kl;
            wsm[c * 192 + (((k >> 2) ^ ((c >> 2) & 7)) << 2) + (k & 3)] = xall[i];
        }
        __syncthreads();
    }
    if (threadIdx.x < 128) bsm[threadIdx.x] = bap[threadIdx.x];
    __syncthreads();

    const int lane = threadIdx.x & 31;
    const int warp = threadIdx.x >> 5;
    const int gw   = blockIdx.x * 8 + warp;
    const int nw   = gridDim.x * 8;
    const int s7   = lane & 7;

    float* xw = xall + warp * (8 * 196);
    const float* wl = wsm + (lane * 4) * 192;
    const float4 bias4 = *reinterpret_cast<const float4*>(bsm + lane * 4);

    const int h  = lane >> 4;
    const int j  = lane & 15;
    const int cg = j * 12;

    unsigned long long acc[8][4];
    #pragma unroll
    for (int e = 0; e < 8; ++e)
        #pragma unroll
        for (int c = 0; c < 4; ++c) acc[e][c] = 0ull;

    const int tiles = (N + 7) >> 3;
    for (int tile = gw; tile < tiles; tile += nw) {
        const int base = tile * 8;

        #pragma unroll
        for (int r = 0; r < 4; ++r) {
            int nl = r * 2 + h;
            int ng = base + nl;
            if (ng < N) {
                #pragma unroll
                for (int q = 0; q < 3; ++q) {
                    int off = cg + q * 4;
                    float4 v;
                    if (off < D_IN)
                        v = *reinterpret_cast<const float4*>(nfeats + (size_t)ng * D_IN + off);
                    else
                        v = *reinterpret_cast<const float4*>(g_hneigh + (size_t)ng * D_OUT + (off - D_IN));
                    *reinterpret_cast<float4*>(xw + nl * 196 + off) = v;
                }
            }
        }
        __syncwarp();

        #pragma unroll 4
        for (int t = 0; t < 48; ++t) {
            const int wq = ((t ^ s7) << 2);
            ulonglong2 w0 = *reinterpret_cast<const ulonglong2*>(wl + wq);
            ulonglong2 w1 = *reinterpret_cast<const ulonglong2*>(wl + 192 + wq);
            ulonglong2 w2 = *reinterpret_cast<const ulonglong2*>(wl + 384 + wq);
            ulonglong2 w3 = *reinterpret_cast<const ulonglong2*>(wl + 576 + wq);
            #pragma unroll
            for (int e = 0; e < 8; ++e) {
                ulonglong2 xv = *reinterpret_cast<const ulonglong2*>(xw + e * 196 + t * 4);
                ffma2(acc[e][0], xv.x, w0.x); ffma2(acc[e][0], xv.y, w0.y);
                ffma2(acc[e][1], xv.x, w1.x); ffma2(acc[e][1], xv.y, w1.y);
                ffma2(acc[e][2], xv.x, w2.x); ffma2(acc[e][2], xv.y, w2.y);
                ffma2(acc[e][3], xv.x, w3.x); ffma2(acc[e][3], xv.y, w3.y);
            }
        }

        #pragma unroll
        for (int e = 0; e < 8; ++e) {
            int ng = base + e;
            float2 f0 = unpack2(acc[e][0]);
            float2 f1 = unpack2(acc[e][1]);
            float2 f2 = unpack2(acc[e][2]);
            float2 f3 = unpack2(acc[e][3]);
            float4 o;
            o.x = fmaxf(f0.x + f0.y + bias4.x, 0.f);
            o.y = fmaxf(f1.x + f1.y + bias4.y, 0.f);
            o.z = fmaxf(f2.x + f2.y + bias4.z, 0.f);
            o.w = fmaxf(f3.x + f3.y + bias4.w, 0.f);
            if (ng < N)
                *reinterpret_cast<float4*>(out + (size_t)ng * D_OUT + lane * 4) = o;
            acc[e][0] = 0ull; acc[e][1] = 0ull; acc[e][2] = 0ull; acc[e][3] = 0ull;
        }
        __syncwarp();
    }
}

extern "C" void kernel_launch(void* const* d_in, const int* in_sizes, int n_in,
                              void* d_out, int out_size)
{
    const float* nfeats = (const float*)d_in[0];
    const float* efeats = (const float*)d_in[1];
    const float* Wmsg   = (const float*)d_in[2];
    const float* bmsg   = (const float*)d_in[3];
    const float* Wap    = (const float*)d_in[4];
    const float* bap    = (const float*)d_in[5];
    const int*   src    = (const int*)d_in[6];
    const int*   dst    = (const int*)d_in[7];

    const int E = in_sizes[6];
    const int N = in_sizes[0] / D_IN;

    const size_t smem_edge  = SM_EDGE_BYTES;                    // 197120 B
    const size_t smem_apply = A_SMEM_FLOATS * sizeof(float);    // 148992 B
    cudaFuncSetAttribute(edge_msg_kernel, cudaFuncAttributeMaxDynamicSharedMemorySize, (int)smem_edge);
    cudaFuncSetAttribute(apply_kernel,    cudaFuncAttributeMaxDynamicSharedMemorySize, (int)smem_apply);

    unsigned char* nconv_p; cudaGetSymbolAddress((void**)&nconv_p, g_nconv);
    unsigned char* econv_p; cudaGetSymbolAddress((void**)&econv_p, g_econv);

    // prepass conversions
    {
        int nchunks = N * 16;
        conv_split_kernel<<<(nchunks + 255) / 256, 256>>>(
            (const float4*)nfeats, nconv_p, nchunks);
        int echunks = E * 16;
        conv_split_kernel<<<(echunks + 255) / 256, 256>>>(
            (const float4*)efeats, econv_p, echunks);
    }

    const int n4 = (N * D_OUT) / 4;
    zero_hneigh_kernel<<<(n4 + 255) / 256, 256>>>(n4);
    edge_msg_kernel<<<148, 256, smem_edge>>>(Wmsg, bmsg, src, dst, E);
    apply_kernel<<<152, 256, smem_apply>>>(nfeats, Wap, bap, (float*)d_out, N);
}

// round 8
// speedup vs baseline: 1.6839x; 1.1553x over previous
#include <cuda_runtime.h>
#include <cstdint>

#define D_IN 64
#define D_E 64
#define D_MSG_IN 128
#define D_OUT 128
#define D_APPLY_IN 192
#define MAX_NODES 50000
#define MAX_EDGES 800000

__device__ float g_hneigh[MAX_NODES * D_OUT];
// packed bf16 split rows: per row 128B hi + 128B lo
__device__ __align__(16) unsigned char g_nconv[(size_t)MAX_NODES * 256];
__device__ __align__(16) unsigned char g_econv[(size_t)MAX_EDGES * 256];

// ============================ helpers ============================
__device__ __forceinline__ void ffma2(unsigned long long& acc,
                                      unsigned long long a, unsigned long long b) {
    asm("fma.rn.f32x2 %0, %1, %2, %0;" : "+l"(acc) : "l"(a), "l"(b));
}
__device__ __forceinline__ float2 unpack2(unsigned long long v) {
    float2 f;
    asm("mov.b64 {%0, %1}, %2;" : "=f"(f.x), "=f"(f.y) : "l"(v));
    return f;
}
__device__ __forceinline__ void red_add_v4(float* p, float a, float b, float c, float d) {
    asm volatile("red.global.add.v4.f32 [%0], {%1, %2, %3, %4};"
                 :: "l"(p), "f"(a), "f"(b), "f"(c), "f"(d) : "memory");
}
__device__ __forceinline__ uint32_t smem_u32(const void* p) {
    uint32_t a;
    asm("{ .reg .u64 t; cvta.to.shared.u64 t, %1; cvt.u32.u64 %0, t; }" : "=r"(a) : "l"(p));
    return a;
}
__device__ __forceinline__ void ldsm4(uint32_t* r, uint32_t addr) {
    asm volatile("ldmatrix.sync.aligned.m8n8.x4.shared.b16 {%0,%1,%2,%3}, [%4];"
                 : "=r"(r[0]), "=r"(r[1]), "=r"(r[2]), "=r"(r[3]) : "r"(addr));
}
__device__ __forceinline__ void mma_bf16(float* c, const uint32_t* a, uint32_t b0, uint32_t b1) {
    asm volatile("mma.sync.aligned.m16n8k16.row.col.f32.bf16.bf16.f32 "
                 "{%0,%1,%2,%3}, {%4,%5,%6,%7}, {%8,%9}, {%0,%1,%2,%3};"
                 : "+f"(c[0]), "+f"(c[1]), "+f"(c[2]), "+f"(c[3])
                 : "r"(a[0]), "r"(a[1]), "r"(a[2]), "r"(a[3]), "r"(b0), "r"(b1));
}
__device__ __forceinline__ void cpa16(uint32_t dst, const void* src) {
    asm volatile("cp.async.cg.shared.global [%0], [%1], 16;" :: "r"(dst), "l"(src));
}
#define CP_COMMIT() asm volatile("cp.async.commit_group;" ::: "memory")
#define CP_WAIT0()  asm volatile("cp.async.wait_group 0;" ::: "memory")
__device__ __forceinline__ void sts_zero16(uint32_t dst) {
    asm volatile("st.shared.v4.b32 [%0], {%1,%1,%1,%1};" :: "r"(dst), "r"(0u));
}

__global__ void zero_hneigh_kernel(int n4) {
    int i = blockIdx.x * blockDim.x + threadIdx.x;
    if (i < n4)
        reinterpret_cast<float4*>(g_hneigh)[i] = make_float4(0.f, 0.f, 0.f, 0.f);
}

// ---------- prepass: fp32 rows -> packed bf16 hi/lo rows (256B/row) ----------
__global__ void conv_split_kernel(const float4* __restrict__ in,
                                  unsigned char* __restrict__ out, int nchunks) {
    int i = blockIdx.x * blockDim.x + threadIdx.x;
    if (i >= nchunks) return;
    int row = i >> 4, q = i & 15;
    float4 v = in[i];
    uint32_t h01, h23;
    asm("cvt.rn.bf16x2.f32 %0, %1, %2;" : "=r"(h01) : "f"(v.y), "f"(v.x));
    asm("cvt.rn.bf16x2.f32 %0, %1, %2;" : "=r"(h23) : "f"(v.w), "f"(v.z));
    float hx = __uint_as_float(h01 << 16);
    float hy = __uint_as_float(h01 & 0xffff0000u);
    float hz = __uint_as_float(h23 << 16);
    float hw = __uint_as_float(h23 & 0xffff0000u);
    uint32_t l01, l23;
    asm("cvt.rn.bf16x2.f32 %0, %1, %2;" : "=r"(l01) : "f"(v.y - hy), "f"(v.x - hx));
    asm("cvt.rn.bf16x2.f32 %0, %1, %2;" : "=r"(l23) : "f"(v.w - hw), "f"(v.z - hz));
    unsigned char* o = out + (size_t)row * 256;
    *reinterpret_cast<uint2*>(o + q * 8)       = make_uint2(h01, h23);
    *reinterpret_cast<uint2*>(o + 128 + q * 8) = make_uint2(l01, l23);
}

// =====================================================================
// Edge kernel v6: 512 threads (16 warps, warp tile m32 x n32),
// single barrier per tile, double-buffered cp.async, split-2 bf16 mma.
// =====================================================================
#define SM_WHI  0u
#define SM_WLO  32768u
#define SM_XHI0 65536u
#define SM_XLO0 98304u
#define SM_XHI1 131072u
#define SM_XLO1 163840u
#define SM_BIAS 196608u
#define SM_EDGE_BYTES 197120u

// byte offset inside a 128x128-bf16 tile: 256B rows, 16B-chunk XOR swizzle
__device__ __forceinline__ uint32_t toff(int row, int kchunk) {
    return ((uint32_t)row << 8) + ((uint32_t)(kchunk ^ (row & 7)) << 4);
}

__global__ __launch_bounds__(512, 1)
void edge_msg_kernel(const float* __restrict__ Wmsg,
                     const float* __restrict__ bmsg,
                     const int* __restrict__ src,
                     const int* __restrict__ dst,
                     int E)
{
    extern __shared__ char smem[];
    const uint32_t sb = smem_u32(smem);
    const int tid  = threadIdx.x;
    const int lane = tid & 31;
    const int wid  = tid >> 5;

    // ---- W split to smem: Wt[n][k] = Wmsg[k][n], hi/lo bf16, swizzled ----
    for (int i = tid; i < 128 * 128; i += 512) {
        int n = i >> 7, k = i & 127;
        float w = Wmsg[k * 128 + n];
        uint32_t hb;
        asm("cvt.rn.bf16x2.f32 %0, %1, %2;" : "=r"(hb) : "f"(0.f), "f"(w));
        float hf = __uint_as_float(hb << 16);
        uint32_t lb;
        asm("cvt.rn.bf16x2.f32 %0, %1, %2;" : "=r"(lb) : "f"(0.f), "f"(w - hf));
        uint32_t off = toff(n, k >> 3) + (k & 7) * 2;
        *reinterpret_cast<uint16_t*>(smem + SM_WHI + off) = (uint16_t)hb;
        *reinterpret_cast<uint16_t*>(smem + SM_WLO + off) = (uint16_t)lb;
    }
    if (tid < 128) reinterpret_cast<float*>(smem + SM_BIAS)[tid] = bmsg[tid];
    __syncthreads();

    // ---- gather constants: warp handles 8 rows; lane: (row, half, quarter) ----
    const int g_r    = lane & 7;            // row within warp's 8
    const int g_row  = (wid << 3) + g_r;    // tile row 0..127
    const int g_half = (lane >> 3) & 1;     // 0 = node feats, 1 = edge feats
    const int g_quart = lane >> 4;          // chunk group 0..3 / 4..7

    // ---- warp tiling for MMA: 4(m) x 4(n), warp tile m32 x n32 ----
    const int mbase = (wid & 3) * 32;
    const int nbase = (wid >> 2) * 32;
    const int mrel  = lane & 15;
    const int khA   = lane >> 4;
    const int nrel  = (lane & 7) + ((lane >> 4) << 3);
    const int khB   = (lane >> 3) & 1;
    const uint32_t swzA = (uint32_t)(mrel & 7);
    const uint32_t swzB = (uint32_t)(nrel & 7);
    uint32_t aRow[2], bRow[2];
    #pragma unroll
    for (int mt = 0; mt < 2; ++mt) aRow[mt] = (uint32_t)(mbase + mt * 16 + mrel) << 8;
    #pragma unroll
    for (int g = 0; g < 2; ++g) bRow[g] = (uint32_t)(nbase + g * 16 + nrel) << 8;

    // bias pairs: c = nbase + nt*8 + (lane&3)*2
    float bx[4], by[4];
    {
        const float* bsm = reinterpret_cast<const float*>(smem + SM_BIAS);
        #pragma unroll
        for (int nt = 0; nt < 4; ++nt) {
            float2 bb = *reinterpret_cast<const float2*>(bsm + nbase + nt * 8 + (lane & 3) * 2);
            bx[nt] = bb.x; by[nt] = bb.y;
        }
    }

    float acc[2][4][4];
    #pragma unroll
    for (int mt = 0; mt < 2; ++mt)
        #pragma unroll
        for (int nt = 0; nt < 4; ++nt)
            #pragma unroll
            for (int q = 0; q < 4; ++q) acc[mt][nt][q] = 0.f;

    const uint32_t xhiS[2] = {sb + SM_XHI0, sb + SM_XHI1};
    const uint32_t xloS[2] = {sb + SM_XLO0, sb + SM_XLO1};
    const uint32_t wHi = sb + SM_WHI, wLo = sb + SM_WLO;

    const int tiles = (E + 127) >> 7;
    const int grid  = gridDim.x;

    // ---- gather one tile into a stage (8 cpa16 per thread, convergent) ----
    auto issue_tile = [&](int base, uint32_t xhi, uint32_t xlo) {
        int sv = 0;
        {
            int ee = base + (wid << 3) + (lane & 7);
            if (lane < 8 && ee < E) sv = src[ee];
        }
        const int s  = __shfl_sync(0xffffffffu, sv, g_r);   // all lanes participate
        const int eg = base + g_row;
        const bool valid = (eg < E);
        const unsigned char* srow = (g_half == 0)
            ? (g_nconv + (size_t)s * 256)
            : (g_econv + (size_t)eg * 256);
        #pragma unroll
        for (int c = 0; c < 4; ++c) {
            const int cl = (g_quart << 2) + c;      // local chunk 0..7
            const int kchunk = (g_half << 3) + cl;  // tile kchunk 0..15
            const uint32_t dhi = xhi + toff(g_row, kchunk);
            const uint32_t dlo = xlo + toff(g_row, kchunk);
            if (valid) {
                cpa16(dhi, srow + cl * 16);
                cpa16(dlo, srow + 128 + cl * 16);
            } else {
                sts_zero16(dhi);
                sts_zero16(dlo);
            }
        }
    };

    // ---- pipelined main loop: ONE barrier per tile ----
    int t = blockIdx.x;
    int cur = 0;
    if (t < tiles) issue_tile(t << 7, xhiS[0], xloS[0]);
    CP_COMMIT();

    for (; t < tiles; t += grid) {
        CP_WAIT0();
        __syncthreads();   // publishes stage cur; proves all warps done with cur^1

        const int tn = t + grid;
        if (tn < tiles) issue_tile(tn << 7, xhiS[cur ^ 1], xloS[cur ^ 1]);
        CP_COMMIT();

        const uint32_t xhi = xhiS[cur], xlo = xloS[cur];
        const int base = t << 7;

        // ---- MMA: Xhi*Whi + Xlo*Whi + Xhi*Wlo ----
        #pragma unroll
        for (int kc = 0; kc < 8; ++kc) {
            const uint32_t ka = (uint32_t)(((kc << 1) | khA) ^ swzA) << 4;
            const uint32_t kb = (uint32_t)(((kc << 1) | khB) ^ swzB) << 4;
            uint32_t ahi[2][4], alo[2][4], bfr[2][4];
            #pragma unroll
            for (int mt = 0; mt < 2; ++mt) ldsm4(ahi[mt], xhi + aRow[mt] + ka);
            #pragma unroll
            for (int mt = 0; mt < 2; ++mt) ldsm4(alo[mt], xlo + aRow[mt] + ka);
            #pragma unroll
            for (int g = 0; g < 2; ++g) ldsm4(bfr[g], wHi + bRow[g] + kb);
            #pragma unroll
            for (int mt = 0; mt < 2; ++mt)
                #pragma unroll
                for (int nt = 0; nt < 4; ++nt)
                    mma_bf16(acc[mt][nt], ahi[mt],
                             bfr[nt >> 1][(nt & 1) * 2], bfr[nt >> 1][(nt & 1) * 2 + 1]);
            #pragma unroll
            for (int mt = 0; mt < 2; ++mt)
                #pragma unroll
                for (int nt = 0; nt < 4; ++nt)
                    mma_bf16(acc[mt][nt], alo[mt],
                             bfr[nt >> 1][(nt & 1) * 2], bfr[nt >> 1][(nt & 1) * 2 + 1]);
            #pragma unroll
            for (int g = 0; g < 2; ++g) ldsm4(bfr[g], wLo + bRow[g] + kb);
            #pragma unroll
            for (int mt = 0; mt < 2; ++mt)
                #pragma unroll
                for (int nt = 0; nt < 4; ++nt)
                    mma_bf16(acc[mt][nt], ahi[mt],
                             bfr[nt >> 1][(nt & 1) * 2], bfr[nt >> 1][(nt & 1) * 2 + 1]);
        }

        // ---- epilogue: bias+relu, pair-merge via shfl, red.v4 scatter ----
        #pragma unroll
        for (int mt = 0; mt < 2; ++mt) {
            const int rtop = mbase + mt * 16 + (lane >> 2);
            const int etop = base + rtop;
            const int ebot = etop + 8;
            const int dtop = (etop < E) ? dst[etop] : 0;
            const int dbot = (ebot < E) ? dst[ebot] : 0;
            const int cb   = nbase + (lane & 2) * 2;
            #pragma unroll
            for (int nt = 0; nt < 4; ++nt) {
                float v0 = fmaxf(acc[mt][nt][0] + bx[nt], 0.f);
                float v1 = fmaxf(acc[mt][nt][1] + by[nt], 0.f);
                float v2 = fmaxf(acc[mt][nt][2] + bx[nt], 0.f);
                float v3 = fmaxf(acc[mt][nt][3] + by[nt], 0.f);
                float w0 = __shfl_xor_sync(0xffffffffu, v0, 1);
                float w1 = __shfl_xor_sync(0xffffffffu, v1, 1);
                float w2 = __shfl_xor_sync(0xffffffffu, v2, 1);
                float w3 = __shfl_xor_sync(0xffffffffu, v3, 1);
                if (!(lane & 1)) {
                    if (etop < E)
                        red_add_v4(g_hneigh + (size_t)dtop * D_OUT + cb + nt * 8, v0, v1, w0, w1);
                    if (ebot < E)
                        red_add_v4(g_hneigh + (size_t)dbot * D_OUT + cb + nt * 8, v2, v3, w2, w3);
                }
                acc[mt][nt][0] = 0.f; acc[mt][nt][1] = 0.f;
                acc[mt][nt][2] = 0.f; acc[mt][nt][3] = 0.f;
            }
        }
        cur ^= 1;
    }
}

// =====================================================================
// Apply kernel (R3): 8 nodes/warp, f32x2 packed along k.
// =====================================================================
#define A_WT 0
#define A_BIAS 24576
#define A_X 24704
#define A_SMEM_FLOATS 37248

__global__ __launch_bounds__(256, 1)
void apply_kernel(const float* __restrict__ nfeats,
                  const float* __restrict__ Wap,
                  const float* __restrict__ bap,
                  float* __restrict__ out,
                  int N)
{
    extern __shared__ float sm[];
    float* wsm  = sm + A_WT;
    float* bsm  = sm + A_BIAS;
    float* xall = sm + A_X;

    for (int half = 0; half < 2; ++half) {
        for (int i = threadIdx.x; i < 3072; i += 256)
            reinterpret_cast<float4*>(xall)[i] =
                reinterpret_cast<const float4*>(Wap + half * 12288)[i];
        __syncthreads();
        for (int i = threadIdx.x; i < 12288; i += 256) {
            int kl = i >> 7, c = i & 127, k = half * 96 + kl;
            wsm[c * 192 + (((k >> 2) ^ ((c >> 2) & 7)) << 2) + (k & 3)] = xall[i];
        }
        __syncthreads();
    }
    if (threadIdx.x < 128) bsm[threadIdx.x] = bap[threadIdx.x];
    __syncthreads();

    const int lane = threadIdx.x & 31;
    const int warp = threadIdx.x >> 5;
    const int gw   = blockIdx.x * 8 + warp;
    const int nw   = gridDim.x * 8;
    const int s7   = lane & 7;

    float* xw = xall + warp * (8 * 196);
    const float* wl = wsm + (lane * 4) * 192;
    const float4 bias4 = *reinterpret_cast<const float4*>(bsm + lane * 4);

    const int h  = lane >> 4;
    const int j  = lane & 15;
    const int cg = j * 12;

    unsigned long long acc[8][4];
    #pragma unroll
    for (int e = 0; e < 8; ++e)
        #pragma unroll
        for (int c = 0; c < 4; ++c) acc[e][c] = 0ull;

    const int tiles = (N + 7) >> 3;
    for (int tile = gw; tile < tiles; tile += nw) {
        const int base = tile * 8;

        #pragma unroll
        for (int r = 0; r < 4; ++r) {
            int nl = r * 2 + h;
            int ng = base + nl;
            if (ng < N) {
                #pragma unroll
                for (int q = 0; q < 3; ++q) {
                    int off = cg + q * 4;
                    float4 v;
                    if (off < D_IN)
                        v = *reinterpret_cast<const float4*>(nfeats + (size_t)ng * D_IN + off);
                    else
                        v = *reinterpret_cast<const float4*>(g_hneigh + (size_t)ng * D_OUT + (off - D_IN));
                    *reinterpret_cast<float4*>(xw + nl * 196 + off) = v;
                }
            }
        }
        __syncwarp();

        #pragma unroll 4
        for (int t = 0; t < 48; ++t) {
            const int wq = ((t ^ s7) << 2);
            ulonglong2 w0 = *reinterpret_cast<const ulonglong2*>(wl + wq);
            ulonglong2 w1 = *reinterpret_cast<const ulonglong2*>(wl + 192 + wq);
            ulonglong2 w2 = *reinterpret_cast<const ulonglong2*>(wl + 384 + wq);
            ulonglong2 w3 = *reinterpret_cast<const ulonglong2*>(wl + 576 + wq);
            #pragma unroll
            for (int e = 0; e < 8; ++e) {
                ulonglong2 xv = *reinterpret_cast<const ulonglong2*>(xw + e * 196 + t * 4);
                ffma2(acc[e][0], xv.x, w0.x); ffma2(acc[e][0], xv.y, w0.y);
                ffma2(acc[e][1], xv.x, w1.x); ffma2(acc[e][1], xv.y, w1.y);
                ffma2(acc[e][2], xv.x, w2.x); ffma2(acc[e][2], xv.y, w2.y);
                ffma2(acc[e][3], xv.x, w3.x); ffma2(acc[e][3], xv.y, w3.y);
            }
        }

        #pragma unroll
        for (int e = 0; e < 8; ++e) {
            int ng = base + e;
            float2 f0 = unpack2(acc[e][0]);
            float2 f1 = unpack2(acc[e][1]);
            float2 f2 = unpack2(acc[e][2]);
            float2 f3 = unpack2(acc[e][3]);
            float4 o;
            o.x = fmaxf(f0.x + f0.y + bias4.x, 0.f);
            o.y = fmaxf(f1.x + f1.y + bias4.y, 0.f);
            o.z = fmaxf(f2.x + f2.y + bias4.z, 0.f);
            o.w = fmaxf(f3.x + f3.y + bias4.w, 0.f);
            if (ng < N)
                *reinterpret_cast<float4*>(out + (size_t)ng * D_OUT + lane * 4) = o;
            acc[e][0] = 0ull; acc[e][1] = 0ull; acc[e][2] = 0ull; acc[e][3] = 0ull;
        }
        __syncwarp();
    }
}

extern "C" void kernel_launch(void* const* d_in, const int* in_sizes, int n_in,
                              void* d_out, int out_size)
{
    const float* nfeats = (const float*)d_in[0];
    const float* efeats = (const float*)d_in[1];
    const float* Wmsg   = (const float*)d_in[2];
    const float* bmsg   = (const float*)d_in[3];
    const float* Wap    = (const float*)d_in[4];
    const float* bap    = (const float*)d_in[5];
    const int*   src    = (const int*)d_in[6];
    const int*   dst    = (const int*)d_in[7];

    const int E = in_sizes[6];
    const int N = in_sizes[0] / D_IN;

    const size_t smem_edge  = SM_EDGE_BYTES;                    // 197120 B
    const size_t smem_apply = A_SMEM_FLOATS * sizeof(float);    // 148992 B
    cudaFuncSetAttribute(edge_msg_kernel, cudaFuncAttributeMaxDynamicSharedMemorySize, (int)smem_edge);
    cudaFuncSetAttribute(apply_kernel,    cudaFuncAttributeMaxDynamicSharedMemorySize, (int)smem_apply);

    unsigned char* nconv_p; cudaGetSymbolAddress((void**)&nconv_p, g_nconv);
    unsigned char* econv_p; cudaGetSymbolAddress((void**)&econv_p, g_econv);

    // prepass conversions
    {
        int nchunks = N * 16;
        conv_split_kernel<<<(nchunks + 255) / 256, 256>>>(
            (const float4*)nfeats, nconv_p, nchunks);
        int echunks = E * 16;
        conv_split_kernel<<<(echunks + 255) / 256, 256>>>(
            (const float4*)efeats, econv_p, echunks);
    }

    const int n4 = (N * D_OUT) / 4;
    zero_hneigh_kernel<<<(n4 + 255) / 256, 256>>>(n4);
    edge_msg_kernel<<<148, 512, smem_edge>>>(Wmsg, bmsg, src, dst, E);
    apply_kernel<<<152, 256, smem_apply>>>(nfeats, Wap, bap, (float*)d_out, N);
}

// round 9
// speedup vs baseline: 1.6892x; 1.0031x over previous
#include <cuda_runtime.h>
#include <cstdint>

#define D_IN 64
#define D_E 64
#define D_MSG_IN 128
#define D_OUT 128
#define D_APPLY_IN 192
#define MAX_NODES 50000
#define MAX_EDGES 800000

__device__ float g_hneigh[MAX_NODES * D_OUT];
// packed bf16 split rows: per row 128B hi + 128B lo
__device__ __align__(16) unsigned char g_nconv[(size_t)MAX_NODES * 256];
__device__ __align__(16) unsigned char g_econv[(size_t)MAX_EDGES * 256];

// ============================ helpers ============================
__device__ __forceinline__ void ffma2(unsigned long long& acc,
                                      unsigned long long a, unsigned long long b) {
    asm("fma.rn.f32x2 %0, %1, %2, %0;" : "+l"(acc) : "l"(a), "l"(b));
}
__device__ __forceinline__ float2 unpack2(unsigned long long v) {
    float2 f;
    asm("mov.b64 {%0, %1}, %2;" : "=f"(f.x), "=f"(f.y) : "l"(v));
    return f;
}
__device__ __forceinline__ void red_add_v4(float* p, float a, float b, float c, float d) {
    asm volatile("red.global.add.v4.f32 [%0], {%1, %2, %3, %4};"
                 :: "l"(p), "f"(a), "f"(b), "f"(c), "f"(d) : "memory");
}
__device__ __forceinline__ uint32_t smem_u32(const void* p) {
    uint32_t a;
    asm("{ .reg .u64 t; cvta.to.shared.u64 t, %1; cvt.u32.u64 %0, t; }" : "=r"(a) : "l"(p));
    return a;
}
__device__ __forceinline__ void ldsm4(uint32_t* r, uint32_t addr) {
    asm volatile("ldmatrix.sync.aligned.m8n8.x4.shared.b16 {%0,%1,%2,%3}, [%4];"
                 : "=r"(r[0]), "=r"(r[1]), "=r"(r[2]), "=r"(r[3]) : "r"(addr));
}
__device__ __forceinline__ void mma_bf16(float* c, const uint32_t* a, uint32_t b0, uint32_t b1) {
    asm volatile("mma.sync.aligned.m16n8k16.row.col.f32.bf16.bf16.f32 "
                 "{%0,%1,%2,%3}, {%4,%5,%6,%7}, {%8,%9}, {%0,%1,%2,%3};"
                 : "+f"(c[0]), "+f"(c[1]), "+f"(c[2]), "+f"(c[3])
                 : "r"(a[0]), "r"(a[1]), "r"(a[2]), "r"(a[3]), "r"(b0), "r"(b1));
}
__device__ __forceinline__ void cpa16(uint32_t dst, const void* src) {
    asm volatile("cp.async.cg.shared.global [%0], [%1], 16;" :: "r"(dst), "l"(src));
}
#define CP_COMMIT() asm volatile("cp.async.commit_group;" ::: "memory")
#define CP_WAIT0()  asm volatile("cp.async.wait_group 0;" ::: "memory")
__device__ __forceinline__ void sts_zero16(uint32_t dst) {
    asm volatile("st.shared.v4.b32 [%0], {%1,%1,%1,%1};" :: "r"(dst), "r"(0u));
}

__global__ void zero_hneigh_kernel(int n4) {
    int i = blockIdx.x * blockDim.x + threadIdx.x;
    if (i < n4)
        reinterpret_cast<float4*>(g_hneigh)[i] = make_float4(0.f, 0.f, 0.f, 0.f);
}

// ---------- prepass: fp32 rows -> packed bf16 hi/lo rows (256B/row) ----------
__global__ void conv_split_kernel(const float4* __restrict__ in,
                                  unsigned char* __restrict__ out, int nchunks) {
    int i = blockIdx.x * blockDim.x + threadIdx.x;
    if (i >= nchunks) return;
    int row = i >> 4, q = i & 15;
    float4 v = in[i];
    uint32_t h01, h23;
    asm("cvt.rn.bf16x2.f32 %0, %1, %2;" : "=r"(h01) : "f"(v.y), "f"(v.x));
    asm("cvt.rn.bf16x2.f32 %0, %1, %2;" : "=r"(h23) : "f"(v.w), "f"(v.z));
    float hx = __uint_as_float(h01 << 16);
    float hy = __uint_as_float(h01 & 0xffff0000u);
    float hz = __uint_as_float(h23 << 16);
    float hw = __uint_as_float(h23 & 0xffff0000u);
    uint32_t l01, l23;
    asm("cvt.rn.bf16x2.f32 %0, %1, %2;" : "=r"(l01) : "f"(v.y - hy), "f"(v.x - hx));
    asm("cvt.rn.bf16x2.f32 %0, %1, %2;" : "=r"(l23) : "f"(v.w - hw), "f"(v.z - hz));
    unsigned char* o = out + (size_t)row * 256;
    *reinterpret_cast<uint2*>(o + q * 8)       = make_uint2(h01, h23);
    *reinterpret_cast<uint2*>(o + 128 + q * 8) = make_uint2(l01, l23);
}

// =====================================================================
// Edge kernel v7: 2 CTAs/SM x 256 threads, 64-edge tiles, single-
// buffered cp.async (cross-CTA phase overlap), split-2 bf16 mma.
// =====================================================================
#define SM_WHI  0u
#define SM_WLO  32768u
#define SM_XHI  65536u
#define SM_XLO  81920u
#define SM_BIAS 98304u
#define SM_EDGE_BYTES 98816u

// byte offset inside an (rows x 128)-bf16 tile: 256B rows, 16B-chunk XOR swizzle
__device__ __forceinline__ uint32_t toff(int row, int kchunk) {
    return ((uint32_t)row << 8) + ((uint32_t)(kchunk ^ (row & 7)) << 4);
}

__global__ __launch_bounds__(256, 2)
void edge_msg_kernel(const float* __restrict__ Wmsg,
                     const float* __restrict__ bmsg,
                     const int* __restrict__ src,
                     const int* __restrict__ dst,
                     int E)
{
    extern __shared__ char smem[];
    const uint32_t sb = smem_u32(smem);
    const int tid  = threadIdx.x;
    const int lane = tid & 31;
    const int wid  = tid >> 5;

    // ---- W split to smem: Wt[n][k] = Wmsg[k][n], hi/lo bf16, swizzled ----
    for (int i = tid; i < 128 * 128; i += 256) {
        int n = i >> 7, k = i & 127;
        float w = Wmsg[k * 128 + n];
        uint32_t hb;
        asm("cvt.rn.bf16x2.f32 %0, %1, %2;" : "=r"(hb) : "f"(0.f), "f"(w));
        float hf = __uint_as_float(hb << 16);
        uint32_t lb;
        asm("cvt.rn.bf16x2.f32 %0, %1, %2;" : "=r"(lb) : "f"(0.f), "f"(w - hf));
        uint32_t off = toff(n, k >> 3) + (k & 7) * 2;
        *reinterpret_cast<uint16_t*>(smem + SM_WHI + off) = (uint16_t)hb;
        *reinterpret_cast<uint16_t*>(smem + SM_WLO + off) = (uint16_t)lb;
    }
    if (tid < 128) reinterpret_cast<float*>(smem + SM_BIAS)[tid] = bmsg[tid];
    __syncthreads();

    // ---- gather constants: warp handles 8 of the 64 rows ----
    const int g_r    = lane & 7;           // row within warp's 8
    const int g_row  = (wid << 3) + g_r;   // tile row 0..63
    const int g_half = (lane >> 3) & 1;    // 0 = node feats, 1 = edge feats
    const int g_quart = lane >> 4;         // chunk group

    // ---- warp tiling for MMA: 2(m) x 4(n), warp tile m32 x n32 ----
    const int mbase = (wid & 1) * 32;
    const int nbase = (wid >> 1) * 32;
    const int mrel  = lane & 15;
    const int khA   = lane >> 4;
    const int nrel  = (lane & 7) + ((lane >> 4) << 3);
    const int khB   = (lane >> 3) & 1;
    const uint32_t swzA = (uint32_t)(mrel & 7);
    const uint32_t swzB = (uint32_t)(nrel & 7);
    uint32_t aRow[2], bRow[2];
    #pragma unroll
    for (int mt = 0; mt < 2; ++mt) aRow[mt] = (uint32_t)(mbase + mt * 16 + mrel) << 8;
    #pragma unroll
    for (int g = 0; g < 2; ++g) bRow[g] = (uint32_t)(nbase + g * 16 + nrel) << 8;

    // bias pairs: c = nbase + nt*8 + (lane&3)*2
    float bx[4], by[4];
    {
        const float* bsm = reinterpret_cast<const float*>(smem + SM_BIAS);
        #pragma unroll
        for (int nt = 0; nt < 4; ++nt) {
            float2 bb = *reinterpret_cast<const float2*>(bsm + nbase + nt * 8 + (lane & 3) * 2);
            bx[nt] = bb.x; by[nt] = bb.y;
        }
    }

    float acc[2][4][4];
    #pragma unroll
    for (int mt = 0; mt < 2; ++mt)
        #pragma unroll
        for (int nt = 0; nt < 4; ++nt)
            #pragma unroll
            for (int q = 0; q < 4; ++q) acc[mt][nt][q] = 0.f;

    const uint32_t xhi = sb + SM_XHI, xlo = sb + SM_XLO;
    const uint32_t wHi = sb + SM_WHI, wLo = sb + SM_WLO;

    const int tiles = (E + 63) >> 6;
    const int grid  = gridDim.x;

    // ---- gather one 64-edge tile into the single stage (convergent) ----
    auto issue_tile = [&](int base) {
        int sv = 0;
        {
            int ee = base + (wid << 3) + (lane & 7);
            if (lane < 8 && ee < E) sv = src[ee];
        }
        const int s  = __shfl_sync(0xffffffffu, sv, g_r);   // all lanes participate
        const int eg = base + g_row;
        const bool valid = (eg < E);
        const unsigned char* srow = (g_half == 0)
            ? (g_nconv + (size_t)s * 256)
            : (g_econv + (size_t)eg * 256);
        #pragma unroll
        for (int c = 0; c < 4; ++c) {
            const int cl = (g_quart << 2) + c;      // local chunk 0..7
            const int kchunk = (g_half << 3) + cl;  // tile kchunk 0..15
            const uint32_t dhi = xhi + toff(g_row, kchunk);
            const uint32_t dlo = xlo + toff(g_row, kchunk);
            if (valid) {
                cpa16(dhi, srow + cl * 16);
                cpa16(dlo, srow + 128 + cl * 16);
            } else {
                sts_zero16(dhi);
                sts_zero16(dlo);
            }
        }
    };

    // ---- single-buffer pipeline: gather(t+1) overlaps epilogue(t) + sibling CTA ----
    int t = blockIdx.x;
    if (t < tiles) issue_tile(t << 6);
    CP_COMMIT();

    for (; t < tiles; t += grid) {
        CP_WAIT0();
        __syncthreads();   // stage data from all threads visible

        const int base = t << 6;

        // ---- MMA: Xhi*Whi + Xlo*Whi + Xhi*Wlo ----
        #pragma unroll
        for (int kc = 0; kc < 8; ++kc) {
            const uint32_t ka = (uint32_t)(((kc << 1) | khA) ^ swzA) << 4;
            const uint32_t kb = (uint32_t)(((kc << 1) | khB) ^ swzB) << 4;
            uint32_t ahi[2][4], alo[2][4], bfr[2][4];
            #pragma unroll
            for (int mt = 0; mt < 2; ++mt) ldsm4(ahi[mt], xhi + aRow[mt] + ka);
            #pragma unroll
            for (int mt = 0; mt < 2; ++mt) ldsm4(alo[mt], xlo + aRow[mt] + ka);
            #pragma unroll
            for (int g = 0; g < 2; ++g) ldsm4(bfr[g], wHi + bRow[g] + kb);
            #pragma unroll
            for (int mt = 0; mt < 2; ++mt)
                #pragma unroll
                for (int nt = 0; nt < 4; ++nt)
                    mma_bf16(acc[mt][nt], ahi[mt],
                             bfr[nt >> 1][(nt & 1) * 2], bfr[nt >> 1][(nt & 1) * 2 + 1]);
            #pragma unroll
            for (int mt = 0; mt < 2; ++mt)
                #pragma unroll
                for (int nt = 0; nt < 4; ++nt)
                    mma_bf16(acc[mt][nt], alo[mt],
                             bfr[nt >> 1][(nt & 1) * 2], bfr[nt >> 1][(nt & 1) * 2 + 1]);
            #pragma unroll
            for (int g = 0; g < 2; ++g) ldsm4(bfr[g], wLo + bRow[g] + kb);
            #pragma unroll
            for (int mt = 0; mt < 2; ++mt)
                #pragma unroll
                for (int nt = 0; nt < 4; ++nt)
                    mma_bf16(acc[mt][nt], ahi[mt],
                             bfr[nt >> 1][(nt & 1) * 2], bfr[nt >> 1][(nt & 1) * 2 + 1]);
        }

        __syncthreads();   // all warps finished reading the stage

        // issue next tile's gather now — overlaps our epilogue (and sibling CTA)
        const int tn = t + grid;
        if (tn < tiles) issue_tile(tn << 6);
        CP_COMMIT();

        // ---- epilogue: bias+relu, pair-merge via shfl, red.v4 scatter ----
        #pragma unroll
        for (int mt = 0; mt < 2; ++mt) {
            const int rtop = mbase + mt * 16 + (lane >> 2);
            const int etop = base + rtop;
            const int ebot = etop + 8;
            const int dtop = (etop < E) ? dst[etop] : 0;
            const int dbot = (ebot < E) ? dst[ebot] : 0;
            const int cb   = nbase + (lane & 2) * 2;
            #pragma unroll
            for (int nt = 0; nt < 4; ++nt) {
                float v0 = fmaxf(acc[mt][nt][0] + bx[nt], 0.f);
                float v1 = fmaxf(acc[mt][nt][1] + by[nt], 0.f);
                float v2 = fmaxf(acc[mt][nt][2] + bx[nt], 0.f);
                float v3 = fmaxf(acc[mt][nt][3] + by[nt], 0.f);
                float w0 = __shfl_xor_sync(0xffffffffu, v0, 1);
                float w1 = __shfl_xor_sync(0xffffffffu, v1, 1);
                float w2 = __shfl_xor_sync(0xffffffffu, v2, 1);
                float w3 = __shfl_xor_sync(0xffffffffu, v3, 1);
                if (!(lane & 1)) {
                    if (etop < E)
                        red_add_v4(g_hneigh + (size_t)dtop * D_OUT + cb + nt * 8, v0, v1, w0, w1);
                    if (ebot < E)
                        red_add_v4(g_hneigh + (size_t)dbot * D_OUT + cb + nt * 8, v2, v3, w2, w3);
                }
                acc[mt][nt][0] = 0.f; acc[mt][nt][1] = 0.f;
                acc[mt][nt][2] = 0.f; acc[mt][nt][3] = 0.f;
            }
        }
    }
}

// =====================================================================
// Apply kernel (R3): 8 nodes/warp, f32x2 packed along k.
// =====================================================================
#define A_WT 0
#define A_BIAS 24576
#define A_X 24704
#define A_SMEM_FLOATS 37248

__global__ __launch_bounds__(256, 1)
void apply_kernel(const float* __restrict__ nfeats,
                  const float* __restrict__ Wap,
                  const float* __restrict__ bap,
                  float* __restrict__ out,
                  int N)
{
    extern __shared__ float sm[];
    float* wsm  = sm + A_WT;
    float* bsm  = sm + A_BIAS;
    float* xall = sm + A_X;

    for (int half = 0; half < 2; ++half) {
        for (int i = threadIdx.x; i < 3072; i += 256)
            reinterpret_cast<float4*>(xall)[i] =
                reinterpret_cast<const float4*>(Wap + half * 12288)[i];
        __syncthreads();
        for (int i = threadIdx.x; i < 12288; i += 256) {
            int kl = i >> 7, c = i & 127, k = half * 96 + kl;
            wsm[c * 192 + (((k >> 2) ^ ((c >> 2) & 7)) << 2) + (k & 3)] = xall[i];
        }
        __syncthreads();
    }
    if (threadIdx.x < 128) bsm[threadIdx.x] = bap[threadIdx.x];
    __syncthreads();

    const int lane = threadIdx.x & 31;
    const int warp = threadIdx.x >> 5;
    const int gw   = blockIdx.x * 8 + warp;
    const int nw   = gridDim.x * 8;
    const int s7   = lane & 7;

    float* xw = xall + warp * (8 * 196);
    const float* wl = wsm + (lane * 4) * 192;
    const float4 bias4 = *reinterpret_cast<const float4*>(bsm + lane * 4);

    const int h  = lane >> 4;
    const int j  = lane & 15;
    const int cg = j * 12;

    unsigned long long acc[8][4];
    #pragma unroll
    for (int e = 0; e < 8; ++e)
        #pragma unroll
        for (int c = 0; c < 4; ++c) acc[e][c] = 0ull;

    const int tiles = (N + 7) >> 3;
    for (int tile = gw; tile < tiles; tile += nw) {
        const int base = tile * 8;

        #pragma unroll
        for (int r = 0; r < 4; ++r) {
            int nl = r * 2 + h;
            int ng = base + nl;
            if (ng < N) {
                #pragma unroll
                for (int q = 0; q < 3; ++q) {
                    int off = cg + q * 4;
                    float4 v;
                    if (off < D_IN)
                        v = *reinterpret_cast<const float4*>(nfeats + (size_t)ng * D_IN + off);
                    else
                        v = *reinterpret_cast<const float4*>(g_hneigh + (size_t)ng * D_OUT + (off - D_IN));
                    *reinterpret_cast<float4*>(xw + nl * 196 + off) = v;
                }
            }
        }
        __syncwarp();

        #pragma unroll 4
        for (int t = 0; t < 48; ++t) {
            const int wq = ((t ^ s7) << 2);
            ulonglong2 w0 = *reinterpret_cast<const ulonglong2*>(wl + wq);
            ulonglong2 w1 = *reinterpret_cast<const ulonglong2*>(wl + 192 + wq);
            ulonglong2 w2 = *reinterpret_cast<const ulonglong2*>(wl + 384 + wq);
            ulonglong2 w3 = *reinterpret_cast<const ulonglong2*>(wl + 576 + wq);
            #pragma unroll
            for (int e = 0; e < 8; ++e) {
                ulonglong2 xv = *reinterpret_cast<const ulonglong2*>(xw + e * 196 + t * 4);
                ffma2(acc[e][0], xv.x, w0.x); ffma2(acc[e][0], xv.y, w0.y);
                ffma2(acc[e][1], xv.x, w1.x); ffma2(acc[e][1], xv.y, w1.y);
                ffma2(acc[e][2], xv.x, w2.x); ffma2(acc[e][2], xv.y, w2.y);
                ffma2(acc[e][3], xv.x, w3.x); ffma2(acc[e][3], xv.y, w3.y);
            }
        }

        #pragma unroll
        for (int e = 0; e < 8; ++e) {
            int ng = base + e;
            float2 f0 = unpack2(acc[e][0]);
            float2 f1 = unpack2(acc[e][1]);
            float2 f2 = unpack2(acc[e][2]);
            float2 f3 = unpack2(acc[e][3]);
            float4 o;
            o.x = fmaxf(f0.x + f0.y + bias4.x, 0.f);
            o.y = fmaxf(f1.x + f1.y + bias4.y, 0.f);
            o.z = fmaxf(f2.x + f2.y + bias4.z, 0.f);
            o.w = fmaxf(f3.x + f3.y + bias4.w, 0.f);
            if (ng < N)
                *reinterpret_cast<float4*>(out + (size_t)ng * D_OUT + lane * 4) = o;
            acc[e][0] = 0ull; acc[e][1] = 0ull; acc[e][2] = 0ull; acc[e][3] = 0ull;
        }
        __syncwarp();
    }
}

extern "C" void kernel_launch(void* const* d_in, const int* in_sizes, int n_in,
                              void* d_out, int out_size)
{
    const float* nfeats = (const float*)d_in[0];
    const float* efeats = (const float*)d_in[1];
    const float* Wmsg   = (const float*)d_in[2];
    const float* bmsg   = (const float*)d_in[3];
    const float* Wap    = (const float*)d_in[4];
    const float* bap    = (const float*)d_in[5];
    const int*   src    = (const int*)d_in[6];
    const int*   dst    = (const int*)d_in[7];

    const int E = in_sizes[6];
    const int N = in_sizes[0] / D_IN;

    const size_t smem_edge  = SM_EDGE_BYTES;                    // 98816 B (2 CTAs/SM)
    const size_t smem_apply = A_SMEM_FLOATS * sizeof(float);    // 148992 B
    cudaFuncSetAttribute(edge_msg_kernel, cudaFuncAttributeMaxDynamicSharedMemorySize, (int)smem_edge);
    cudaFuncSetAttribute(apply_kernel,    cudaFuncAttributeMaxDynamicSharedMemorySize, (int)smem_apply);

    unsigned char* nconv_p; cudaGetSymbolAddress((void**)&nconv_p, g_nconv);
    unsigned char* econv_p; cudaGetSymbolAddress((void**)&econv_p, g_econv);

    // prepass conversions
    {
        int nchunks = N * 16;
        conv_split_kernel<<<(nchunks + 255) / 256, 256>>>(
            (const float4*)nfeats, nconv_p, nchunks);
        int echunks = E * 16;
        conv_split_kernel<<<(echunks + 255) / 256, 256>>>(
            (const float4*)efeats, econv_p, echunks);
    }

    const int n4 = (N * D_OUT) / 4;
    zero_hneigh_kernel<<<(n4 + 255) / 256, 256>>>(n4);
    edge_msg_kernel<<<296, 256, smem_edge>>>(Wmsg, bmsg, src, dst, E);
    apply_kernel<<<152, 256, smem_apply>>>(nfeats, Wap, bap, (float*)d_out, N);
}